// round 10
// baseline (speedup 1.0000x reference)
#include <cuda_runtime.h>
#include <cuda_fp16.h>
#include <stdint.h>
#include <math.h>

#define BATCH  4096
#define HIDDEN 1024
#define INPUT  512
#define NOUT   4096
#define KTOT   1536
#define BM     128
#define BN     128
#define BK     64
#define NCH    (KTOT / BK)          // 24
#define STAGES 3
#define TILE_B (BM * BK * 2)        // 16384 B
#define STAGE_B (2 * TILE_B)        // 32768 B
#define SMEM_B  (STAGES * STAGE_B)  // 98304 B -> 2 CTAs/SM

// ---------------- device scratch ----------------
__device__ __half g_lin[(size_t)BATCH * NOUT];   // fp16 lin scratch (32 MB)
__device__ __half g_A[(size_t)BATCH * KTOT];
__device__ __half g_B[(size_t)NOUT  * KTOT];

// ---------------- helpers ----------------
__device__ __forceinline__ uint32_t smem_u32(const void* p) {
    uint32_t a;
    asm("{ .reg .u64 t; cvta.to.shared.u64 t, %1; cvt.u32.u64 %0, t; }" : "=r"(a) : "l"(p));
    return a;
}
#define CP16(dst, src) \
    asm volatile("cp.async.cg.shared.global [%0], [%1], 16;" :: "r"(dst), "l"(src) : "memory")
#define CP_COMMIT() asm volatile("cp.async.commit_group;" ::: "memory")
#define CP_WAIT(n)  asm volatile("cp.async.wait_group %0;" :: "n"(n) : "memory")

__device__ __forceinline__ void ldsm4(uint32_t* r, uint32_t addr) {
    asm volatile("ldmatrix.sync.aligned.m8n8.x4.shared.b16 {%0,%1,%2,%3}, [%4];"
                 : "=r"(r[0]), "=r"(r[1]), "=r"(r[2]), "=r"(r[3]) : "r"(addr));
}
__device__ __forceinline__ void mma16816(float* d, const uint32_t* a,
                                         uint32_t b0, uint32_t b1) {
    asm volatile("mma.sync.aligned.m16n8k16.row.col.f32.f16.f16.f32 "
                 "{%0,%1,%2,%3}, {%4,%5,%6,%7}, {%8,%9}, {%0,%1,%2,%3};"
                 : "+f"(d[0]), "+f"(d[1]), "+f"(d[2]), "+f"(d[3])
                 : "r"(a[0]), "r"(a[1]), "r"(a[2]), "r"(a[3]), "r"(b0), "r"(b1));
}
__device__ __forceinline__ uint32_t saddr(uint32_t tile, int row, int c) {
    return tile + (uint32_t)(row * 128) + ((uint32_t)((c ^ (row & 7)) << 4));
}

// ---------------- fp16 conversion: A = [x|h], B = [wih|whh] ----------------
__global__ __launch_bounds__(256)
void lnlstm_convert(const float* __restrict__ x,  const float* __restrict__ h,
                    const float* __restrict__ wi, const float* __restrict__ wh)
{
    const uint32_t idx = blockIdx.x * 256u + threadIdx.x;
    const uint32_t e0  = idx * 4u;
    const int row = e0 / KTOT;
    const int col = e0 % KTOT;
    const float* s1 = blockIdx.y ? wi : x;
    const float* s2 = blockIdx.y ? wh : h;
    float4 v;
    if (col < INPUT) v = *(const float4*)(s1 + (size_t)row * INPUT  + col);
    else             v = *(const float4*)(s2 + (size_t)row * HIDDEN + (col - INPUT));
    __half* dst = blockIdx.y ? g_B : g_A;
    __half2 p0 = __floats2half2_rn(v.x, v.y);
    __half2 p1 = __floats2half2_rn(v.z, v.w);
    uint2 u;
    u.x = *(uint32_t*)&p0;
    u.y = *(uint32_t*)&p1;
    *(uint2*)(dst + e0) = u;    // single 8B store
}

// ---------------- GEMM: g_lin = A * B^T (fp16 mma.sync, fp32 accum) ----------------
// CTA 128x128, 8 warps as 2(M) x 4(N), warp tile 64x32. 3 stages, 2 CTAs/SM.
__global__ void __launch_bounds__(256, 2)
lnlstm_mma_gemm()
{
    extern __shared__ char smem[];
    const uint32_t sb = smem_u32(smem);
    const int tid  = threadIdx.x;
    const int wid  = tid >> 5;
    const int lane = tid & 31;
    const int m0 = blockIdx.y * BM;
    const int n0 = blockIdx.x * BN;

    const int trow = tid >> 1;
    const int tc0  = (tid & 1) * 4;
    const __half* gA = g_A + (size_t)(m0 + trow) * KTOT + tc0 * 8;
    const __half* gB = g_B + (size_t)(n0 + trow) * KTOT + tc0 * 8;
    uint32_t dofs[4];
    #pragma unroll
    for (int c = 0; c < 4; ++c)
        dofs[c] = (uint32_t)(trow * 128) + ((uint32_t)(((tc0 + c) ^ (trow & 7)) << 4));

    const int sub = lane >> 3, r8 = lane & 7;
    const int rA  = (wid >> 2) * 64 + (sub & 1) * 8 + r8;
    const int cA  = sub >> 1;
    const int rB  = (wid & 3) * 32 + (sub >> 1) * 8 + r8;
    const int cB  = sub & 1;

    float acc[4][4][4];
    #pragma unroll
    for (int i = 0; i < 4; ++i)
        #pragma unroll
        for (int j = 0; j < 4; ++j)
            #pragma unroll
            for (int q = 0; q < 4; ++q) acc[i][j][q] = 0.f;

    auto load_stage = [&](int ch, int s) {
        const uint32_t base = sb + (uint32_t)s * STAGE_B;
        const size_t ke = (size_t)ch * BK;
        #pragma unroll
        for (int c = 0; c < 4; ++c) {
            CP16(base + dofs[c],          gA + ke + c * 8);
            CP16(base + TILE_B + dofs[c], gB + ke + c * 8);
        }
    };

    load_stage(0, 0); CP_COMMIT();
    load_stage(1, 1); CP_COMMIT();

    #pragma unroll 1
    for (int ch = 0; ch < NCH; ++ch) {
        CP_WAIT(1);
        __syncthreads();
        if (ch + STAGES - 1 < NCH)
            load_stage(ch + STAGES - 1, (ch + STAGES - 1) % STAGES);
        CP_COMMIT();

        const uint32_t stb = sb + (uint32_t)(ch % STAGES) * STAGE_B;
        const uint32_t tA = stb, tB = stb + TILE_B;

        #pragma unroll
        for (int ks = 0; ks < 4; ++ks) {
            uint32_t a[4][4], b[2][4];
            #pragma unroll
            for (int mi = 0; mi < 4; ++mi)
                ldsm4(a[mi], saddr(tA, rA + mi * 16, ks * 2 + cA));
            #pragma unroll
            for (int ng = 0; ng < 2; ++ng)
                ldsm4(b[ng], saddr(tB, rB + ng * 16, ks * 2 + cB));
            #pragma unroll
            for (int mi = 0; mi < 4; ++mi) {
                #pragma unroll
                for (int ni = 0; ni < 4; ++ni) {
                    const int g = ni >> 1, o = (ni & 1) * 2;
                    mma16816(acc[mi][ni], a[mi], b[g][o], b[g][o + 1]);
                }
            }
        }
    }

    const int g = lane >> 2, tq = lane & 3;
    #pragma unroll
    for (int mi = 0; mi < 4; ++mi) {
        const int row = m0 + (wid >> 2) * 64 + mi * 16 + g;
        #pragma unroll
        for (int ni = 0; ni < 4; ++ni) {
            const int col = n0 + (wid & 3) * 32 + ni * 8 + tq * 2;
            __half* p = g_lin + (size_t)row * NOUT + col;
            *(__half2*)p                      = __floats2half2_rn(acc[mi][ni][0], acc[mi][ni][1]);
            *(__half2*)(p + (size_t)8 * NOUT) = __floats2half2_rn(acc[mi][ni][2], acc[mi][ni][3]);
        }
    }
}

// ---------------- epilogue: warp-per-row, barrier-free ----------------
__device__ __forceinline__ float fsig(float x)  { return 1.0f / (1.0f + __expf(-x)); }
__device__ __forceinline__ float ftanh(float x) { return 1.0f - 2.0f / (1.0f + __expf(2.0f * x)); }
__device__ __forceinline__ float wredsum(float v) {
    #pragma unroll
    for (int o = 16; o > 0; o >>= 1) v += __shfl_xor_sync(0xffffffffu, v, o);
    return v;
}

__global__ __launch_bounds__(256, 2)
void lnlstm_epilogue(const float* __restrict__ c,
                     const float* __restrict__ lnw_h, const float* __restrict__ lnb_h,
                     const float* __restrict__ lnw_c, const float* __restrict__ lnb_c,
                     float* __restrict__ h_out, float* __restrict__ c_out)
{
    const int wrp = threadIdx.x >> 5;
    const int l   = threadIdx.x & 31;
    const int b   = blockIdx.x * 8 + wrp;               // one warp = one row
    const __half2* row2 = (const __half2*)(g_lin + (size_t)b * NOUT);   // 2048 half2
    const float inv = 1.0f / HIDDEN;

    // phase 1: load all 4 gates (held as half2), accumulate sum/sumsq in fp32
    __half2 v[4][16];
    float mu[4], rs[4];
    #pragma unroll
    for (int g = 0; g < 4; ++g) {
        float s = 0.f, q = 0.f;
        #pragma unroll
        for (int p = 0; p < 16; ++p) {
            v[g][p] = row2[g * 512 + p * 32 + l];
            const float2 f = __half22float2(v[g][p]);
            s += f.x + f.y;
            q += f.x * f.x + f.y * f.y;
        }
        s = wredsum(s); q = wredsum(q);
        mu[g] = s * inv;
        rs[g] = rsqrtf(q * inv - mu[g] * mu[g] + 1e-5f);
    }

    // phase 2: normalize + gates + cell update, accumulate cell stats
    float2  cn[16];
    __half2 og[16];
    float s2 = 0.f, q2 = 0.f;
    #pragma unroll
    for (int p = 0; p < 16; ++p) {
        const int jo = p * 32 + l;                       // half2 index within HIDDEN
        const float2 iv = __half22float2(v[0][p]);
        const float2 fv = __half22float2(v[1][p]);
        const float2 ov = __half22float2(v[2][p]);
        const float2 cv = __half22float2(v[3][p]);
        const float2 lwi = ((const float2*)lnw_h)[jo];
        const float2 lbi = ((const float2*)lnb_h)[jo];
        const float2 lwf = ((const float2*)lnw_h)[512 + jo];
        const float2 lbf = ((const float2*)lnb_h)[512 + jo];
        const float2 lwo = ((const float2*)lnw_h)[1024 + jo];
        const float2 lbo = ((const float2*)lnb_h)[1024 + jo];
        const float2 lwc2 = ((const float2*)lnw_h)[1536 + jo];
        const float2 lbc2 = ((const float2*)lnb_h)[1536 + jo];
        const float2 cold = ((const float2*)c)[(size_t)b * 512 + jo];

        const float gi_x = (iv.x - mu[0]) * rs[0] * lwi.x + lbi.x;
        const float gi_y = (iv.y - mu[0]) * rs[0] * lwi.y + lbi.y;
        const float gf_x = (fv.x - mu[1]) * rs[1] * lwf.x + lbf.x;
        const float gf_y = (fv.y - mu[1]) * rs[1] * lwf.y + lbf.y;
        const float go_x = (ov.x - mu[2]) * rs[2] * lwo.x + lbo.x;
        const float go_y = (ov.y - mu[2]) * rs[2] * lwo.y + lbo.y;
        const float gc_x = (cv.x - mu[3]) * rs[3] * lwc2.x + lbc2.x;
        const float gc_y = (cv.y - mu[3]) * rs[3] * lwc2.y + lbc2.y;

        cn[p].x = fsig(gf_x + 1.0f) * cold.x + fsig(gi_x) * ftanh(gc_x);
        cn[p].y = fsig(gf_y + 1.0f) * cold.y + fsig(gi_y) * ftanh(gc_y);
        og[p] = __floats2half2_rn(fsig(go_x), fsig(go_y));
        s2 += cn[p].x + cn[p].y;
        q2 += cn[p].x * cn[p].x + cn[p].y * cn[p].y;
    }
    s2 = wredsum(s2); q2 = wredsum(q2);
    const float mu2 = s2 * inv;
    const float rs2 = rsqrtf(q2 * inv - mu2 * mu2 + 1e-5f);

    // phase 3: cell LN + output
    #pragma unroll
    for (int p = 0; p < 16; ++p) {
        const int jo = p * 32 + l;
        const float2 lwc2 = ((const float2*)lnw_c)[jo];
        const float2 lbc2 = ((const float2*)lnb_c)[jo];
        const float2 ogf = __half22float2(og[p]);
        float2 ho;
        ho.x = ogf.x * ftanh((cn[p].x - mu2) * rs2 * lwc2.x + lbc2.x);
        ho.y = ogf.y * ftanh((cn[p].y - mu2) * rs2 * lwc2.y + lbc2.y);
        ((float2*)h_out)[(size_t)b * 512 + jo] = ho;
        ((float2*)c_out)[(size_t)b * 512 + jo] = cn[p];
    }
}

// ---------------- launch ----------------
extern "C" void kernel_launch(void* const* d_in, const int* in_sizes, int n_in,
                              void* d_out, int out_size)
{
    const float* x     = (const float*)d_in[0];
    const float* h     = (const float*)d_in[1];
    const float* c     = (const float*)d_in[2];
    const float* wih   = (const float*)d_in[3];
    const float* whh   = (const float*)d_in[4];
    const float* lnw_h = (const float*)d_in[5];
    const float* lnb_h = (const float*)d_in[6];
    const float* lnw_c = (const float*)d_in[7];
    const float* lnb_c = (const float*)d_in[8];

    float* h_out = (float*)d_out;
    float* c_out = h_out + (size_t)BATCH * HIDDEN;

    cudaFuncSetAttribute(lnlstm_mma_gemm,
                         cudaFuncAttributeMaxDynamicSharedMemorySize, SMEM_B);

    lnlstm_convert<<<dim3((BATCH * KTOT / 4) / 256, 2), 256>>>(x, h, wih, whh);
    lnlstm_mma_gemm<<<dim3(NOUT / BN, BATCH / BM), 256, SMEM_B>>>();
    lnlstm_epilogue<<<BATCH / 8, 256>>>(c, lnw_h, lnb_h, lnw_c, lnb_c, h_out, c_out);
}